// round 9
// baseline (speedup 1.0000x reference)
#include <cuda_runtime.h>
#include <cuda_bf16.h>
#include <cstdint>

#define N_NODES 50000
#define E_MAX   625000
#define DIM     128
#define DIM2    (DIM / 2)    // uint32 (bf16x2) per row

// ---------------------------------------------------------------------------
// Static device scratch (no runtime allocation)
// ---------------------------------------------------------------------------
__device__ int      g_cnt[N_NODES];
__device__ int      g_row[N_NODES + 1];
__device__ int      g_cur[N_NODES];
__device__ int      g_bsum[256];
__device__ int      g_bofs[256];
__device__ int      g_esrc[E_MAX];
__device__ float    g_ew[E_MAX];
__device__ float    g_h1[(size_t)N_NODES * DIM];          // layer-1 activations (fp32, for gather)
// bf16 split operand buffers (packed bf16x2 per uint32)
__device__ uint32_t g_xh[(size_t)N_NODES * DIM2];
__device__ uint32_t g_xl[(size_t)N_NODES * DIM2];
__device__ uint32_t g_h1h[(size_t)N_NODES * DIM2];
__device__ uint32_t g_h1l[(size_t)N_NODES * DIM2];
__device__ uint32_t g_hnh[(size_t)N_NODES * DIM2];
__device__ uint32_t g_hnl[(size_t)N_NODES * DIM2];
__device__ uint32_t g_wh[4 * DIM * DIM2];                 // Ws1|Wn1|Ws2|Wn2
__device__ uint32_t g_wl[4 * DIM * DIM2];

#define SCAN_BLK 256
#define SCAN_NB  ((N_NODES + SCAN_BLK - 1) / SCAN_BLK)   // 196

// ---------------------------------------------------------------------------
__device__ __forceinline__ uint32_t packbf(float a, float b) {
    __nv_bfloat162 t = __floats2bfloat162_rn(a, b);
    return *(uint32_t*)&t;
}
__device__ __forceinline__ void split2(float x, float y, uint32_t& hi, uint32_t& lo) {
    float hx = __bfloat162float(__float2bfloat16_rn(x));
    float hy = __bfloat162float(__float2bfloat16_rn(y));
    hi = packbf(hx, hy);
    lo = packbf(x - hx, y - hy);
}

// fp32 -> bf16 hi/lo split, streaming (float2 granularity)
__global__ void split_kernel(const float2* __restrict__ src,
                             uint32_t* __restrict__ hi,
                             uint32_t* __restrict__ lo, int n2) {
    int i = blockIdx.x * blockDim.x + threadIdx.x;
    for (; i < n2; i += gridDim.x * blockDim.x) {
        float2 v = src[i];
        uint32_t h, l;
        split2(v.x, v.y, h, l);
        hi[i] = h;
        lo[i] = l;
    }
}

__global__ void zero_kernel(float4* __restrict__ p, int n4) {
    int i = blockIdx.x * blockDim.x + threadIdx.x;
    float4 z = make_float4(0.f, 0.f, 0.f, 0.f);
    for (; i < n4; i += gridDim.x * blockDim.x) p[i] = z;
}

__global__ void hist_kernel(const int* __restrict__ dst, int* __restrict__ cnt, int E) {
    int i = blockIdx.x * blockDim.x + threadIdx.x;
    for (; i < E; i += gridDim.x * blockDim.x)
        atomicAdd(&cnt[dst[i]], 1);
}

__global__ void scan_bsum_kernel(const int* __restrict__ cnt, int* __restrict__ bsum) {
    __shared__ int sh[SCAN_BLK];
    int i = blockIdx.x * SCAN_BLK + threadIdx.x;
    int v = (i < N_NODES) ? cnt[i] : 0;
    sh[threadIdx.x] = v;
    __syncthreads();
    for (int off = SCAN_BLK / 2; off > 0; off >>= 1) {
        if (threadIdx.x < off) sh[threadIdx.x] += sh[threadIdx.x + off];
        __syncthreads();
    }
    if (threadIdx.x == 0) bsum[blockIdx.x] = sh[0];
}

__global__ void scan_bofs_kernel(const int* __restrict__ bsum,
                                 int* __restrict__ bofs,
                                 int* __restrict__ row) {
    __shared__ int sh[SCAN_BLK];
    int t = threadIdx.x;
    int v = (t < SCAN_NB) ? bsum[t] : 0;
    sh[t] = v;
    __syncthreads();
    for (int off = 1; off < SCAN_BLK; off <<= 1) {
        int u = 0;
        if (t >= off) u = sh[t - off];
        __syncthreads();
        if (t >= off) sh[t] += u;
        __syncthreads();
    }
    if (t < SCAN_NB) bofs[t] = sh[t] - v;
    if (t == SCAN_BLK - 1) row[N_NODES] = sh[t];
}

__global__ void scan_write_kernel(const int* __restrict__ cnt,
                                  const int* __restrict__ bofs,
                                  int* __restrict__ row,
                                  int* __restrict__ cur) {
    __shared__ int sh[SCAN_BLK];
    int t = threadIdx.x;
    int i = blockIdx.x * SCAN_BLK + t;
    int v = (i < N_NODES) ? cnt[i] : 0;
    sh[t] = v;
    __syncthreads();
    for (int off = 1; off < SCAN_BLK; off <<= 1) {
        int u = 0;
        if (t >= off) u = sh[t - off];
        __syncthreads();
        if (t >= off) sh[t] += u;
        __syncthreads();
    }
    if (i < N_NODES) {
        int r = bofs[blockIdx.x] + sh[t] - v;
        row[i] = r;
        cur[i] = r;
    }
}

__global__ void scatter_kernel(const int*   __restrict__ src,
                               const int*   __restrict__ dst,
                               const float* __restrict__ wt,
                               int*   __restrict__ cur,
                               int*   __restrict__ esrc,
                               float* __restrict__ ew,
                               int E)
{
    int i = blockIdx.x * blockDim.x + threadIdx.x;
    for (; i < E; i += gridDim.x * blockDim.x) {
        int p = atomicAdd(&cur[dst[i]], 1);
        esrc[p] = src[i];
        ew[p]   = wt[i];
    }
}

// ---------------------------------------------------------------------------
// Gather v4: one warp per destination node; shfl-broadcast edge batch, MLP=4.
// Output written directly as bf16 hi/lo split (GEMM operand form).
// ---------------------------------------------------------------------------
__global__ void gather_kernel(const float* __restrict__ h,
                              const int*   __restrict__ row,
                              const int*   __restrict__ esrc,
                              const float* __restrict__ ew,
                              uint32_t*    __restrict__ hnh,
                              uint32_t*    __restrict__ hnl)
{
    int warp = (blockIdx.x * blockDim.x + threadIdx.x) >> 5;
    int lane = threadIdx.x & 31;
    if (warp >= N_NODES) return;

    int rs = row[warp];
    int re = row[warp + 1];

    float4 acc = make_float4(0.f, 0.f, 0.f, 0.f);

    for (int base = rs; base < re; base += 32) {
        int cnt = re - base; if (cnt > 32) cnt = 32;
        int   s_l = 0; float w_l = 0.f;
        if (lane < cnt) { s_l = esrc[base + lane]; w_l = ew[base + lane]; }

        for (int j = 0; j < cnt; j += 4) {
            int valid = cnt - j; if (valid > 4) valid = 4;
            float4 v[4]; float wj[4];
#pragma unroll
            for (int u = 0; u < 4; u++) {
                int   s = __shfl_sync(0xffffffffu, s_l, j + u);
                float w = __shfl_sync(0xffffffffu, w_l, j + u);
                if (u < valid) {
                    v[u]  = *(const float4*)(h + (size_t)s * DIM + lane * 4);
                    wj[u] = w;
                }
            }
#pragma unroll
            for (int u = 0; u < 4; u++) {
                if (u < valid) {
                    acc.x += wj[u] * v[u].x;
                    acc.y += wj[u] * v[u].y;
                    acc.z += wj[u] * v[u].z;
                    acc.w += wj[u] * v[u].w;
                }
            }
        }
    }

    float inv = 1.0f / fmaxf((float)(re - rs), 1.0f);
    acc.x *= inv; acc.y *= inv; acc.z *= inv; acc.w *= inv;

    uint32_t h0, l0, h1, l1;
    split2(acc.x, acc.y, h0, l0);
    split2(acc.z, acc.w, h1, l1);
    size_t o = (size_t)warp * DIM2 + lane * 2;
    *(uint2*)(hnh + o) = make_uint2(h0, h1);
    *(uint2*)(hnl + o) = make_uint2(l0, l1);
}

// ---------------------------------------------------------------------------
// SAGE GEMM v8: mma.sync bf16 split-precision; ALL operands preconverted to
// bf16 hi/lo in global. Inner loop: pure load->smem->ldmatrix->mma.
//   out[r, j] = sum_k a[r,k]*W[j,k] (+neighbor half) + b[j]
// CTA: 128x128 tile, 256 threads = 8 warps (4m x 2n); warp tile 32x64.
// K = 256 in 8 chunks of 32. Split math: hi*hi + hi*lo + lo*hi (drop lo*lo).
// ---------------------------------------------------------------------------
#define MM_TILE 128
#define STR 40   // smem row stride in bf16 elems (80B: 16B-aligned, conflict-free ldmatrix)

__device__ __forceinline__ void ldm4(uint32_t (&r)[4], uint32_t addr) {
    asm volatile("ldmatrix.sync.aligned.m8n8.x4.shared.b16 {%0,%1,%2,%3}, [%4];"
                 : "=r"(r[0]), "=r"(r[1]), "=r"(r[2]), "=r"(r[3]) : "r"(addr));
}
__device__ __forceinline__ void mma_bf16(float (&c)[4], const uint32_t (&a)[4],
                                         uint32_t b0, uint32_t b1) {
    asm volatile("mma.sync.aligned.m16n8k16.row.col.f32.bf16.bf16.f32 "
                 "{%0,%1,%2,%3}, {%4,%5,%6,%7}, {%8,%9}, {%0,%1,%2,%3};"
                 : "+f"(c[0]), "+f"(c[1]), "+f"(c[2]), "+f"(c[3])
                 : "r"(a[0]), "r"(a[1]), "r"(a[2]), "r"(a[3]), "r"(b0), "r"(b1));
}
__device__ __forceinline__ uint32_t smem_u32(const void* p) {
    uint32_t a;
    asm("{ .reg .u64 t; cvta.to.shared.u64 t, %1; cvt.u32.u64 %0, t; }" : "=r"(a) : "l"(p));
    return a;
}

__global__ void sage_gemm_mma(const uint32_t* __restrict__ a_hi,   // self operand split
                              const uint32_t* __restrict__ a_lo,
                              const uint32_t* __restrict__ n_hi,   // neighbor operand split
                              const uint32_t* __restrict__ n_lo,
                              const uint32_t* __restrict__ w_hi,   // layer W: [self 8192 | neigh 8192]
                              const uint32_t* __restrict__ w_lo,
                              const float*    __restrict__ bias,
                              float*          __restrict__ out,
                              uint32_t*       __restrict__ o_hi,   // optional split output (layer 1)
                              uint32_t*       __restrict__ o_lo,
                              int nrows, int do_relu)
{
    __shared__ __align__(16) unsigned short Ah[MM_TILE * STR];
    __shared__ __align__(16) unsigned short Al[MM_TILE * STR];
    __shared__ __align__(16) unsigned short Bh[MM_TILE * STR];
    __shared__ __align__(16) unsigned short Bl[MM_TILE * STR];
    __shared__ float bs[DIM];

    int tid  = threadIdx.x;
    int wid  = tid >> 5;
    int lane = tid & 31;
    int warp_m = (wid & 3) * 32;
    int warp_n = (wid >> 2) * 64;
    int rowbase = blockIdx.x * MM_TILE;

    if (tid < DIM) bs[tid] = bias[tid];

    float acc[2][8][4];
#pragma unroll
    for (int mt = 0; mt < 2; mt++)
#pragma unroll
        for (int nt = 0; nt < 8; nt++)
#pragma unroll
            for (int e = 0; e < 4; e++) acc[mt][nt][e] = 0.f;

    uint32_t ah_base = smem_u32(Ah), al_base = smem_u32(Al);
    uint32_t bh_base = smem_u32(Bh), bl_base = smem_u32(Bl);

    // ldmatrix lane address components
    int a_r = lane & 15;
    int a_c = (lane >> 4) << 3;
    int b_g = lane >> 3;
    int b_r = lane & 7;
    int b_nofs = ((b_g >> 1) << 3) + b_r;
    int b_kofs = (b_g & 1) << 3;

    // chunk loader mapping: thread covers row r2, 16-bf16 half `half`
    int r2   = tid >> 1;       // 0..127
    int half = tid & 1;        // 0..1
    int grA = rowbase + r2; if (grA > nrows - 1) grA = nrows - 1;
    size_t a_row_off = (size_t)grA * DIM2 + half * 8;
    size_t w_row_off = (size_t)r2 * DIM2 + half * 8;
    uint32_t sm_off = r2 * STR + half * 16;     // in bf16 elements

    for (int chunk = 0; chunk < 8; chunk++) {
        const uint32_t *pah, *pal, *pwh, *pwl;
        int kb2 = (chunk & 3) * 16;             // k offset in uint32 units
        if (chunk < 4) { pah = a_hi; pal = a_lo; pwh = w_hi;        pwl = w_lo; }
        else           { pah = n_hi; pal = n_lo; pwh = w_hi + 8192; pwl = w_lo + 8192; }

        __syncthreads();   // previous chunk's ldmatrix reads complete

        // ---- load chunk into smem (8 x LDG.128 + 8 x STS.128, no convert) ----
        {
            uint4 vah0 = *(const uint4*)(pah + a_row_off + kb2);
            uint4 vah1 = *(const uint4*)(pah + a_row_off + kb2 + 4);
            uint4 val0 = *(const uint4*)(pal + a_row_off + kb2);
            uint4 val1 = *(const uint4*)(pal + a_row_off + kb2 + 4);
            uint4 vwh0 = *(const uint4*)(pwh + w_row_off + kb2);
            uint4 vwh1 = *(const uint4*)(pwh + w_row_off + kb2 + 4);
            uint4 vwl0 = *(const uint4*)(pwl + w_row_off + kb2);
            uint4 vwl1 = *(const uint4*)(pwl + w_row_off + kb2 + 4);
            *(uint4*)&Ah[sm_off]     = vah0;
            *(uint4*)&Ah[sm_off + 8] = vah1;
            *(uint4*)&Al[sm_off]     = val0;
            *(uint4*)&Al[sm_off + 8] = val1;
            *(uint4*)&Bh[sm_off]     = vwh0;
            *(uint4*)&Bh[sm_off + 8] = vwh1;
            *(uint4*)&Bl[sm_off]     = vwl0;
            *(uint4*)&Bl[sm_off + 8] = vwl1;
        }
        __syncthreads();

        // ---- MMA: 2 k-steps of 16 ----
#pragma unroll
        for (int ks = 0; ks < 2; ks++) {
            int k0 = ks * 16;

            uint32_t ahi[2][4], alo[2][4];
#pragma unroll
            for (int mt = 0; mt < 2; mt++) {
                uint32_t off = (uint32_t)((warp_m + mt * 16 + a_r) * STR + k0 + a_c) * 2;
                ldm4(ahi[mt], ah_base + off);
                ldm4(alo[mt], al_base + off);
            }

#pragma unroll
            for (int h = 0; h < 2; h++) {
                uint32_t bhi[2][4], blo[2][4];
#pragma unroll
                for (int p = 0; p < 2; p++) {
                    int n0 = warp_n + h * 32 + p * 16;
                    uint32_t off = (uint32_t)((n0 + b_nofs) * STR + k0 + b_kofs) * 2;
                    ldm4(bhi[p], bh_base + off);
                    ldm4(blo[p], bl_base + off);
                }
#pragma unroll
                for (int mt = 0; mt < 2; mt++) {
#pragma unroll
                    for (int p = 0; p < 2; p++) {
#pragma unroll
                        for (int s = 0; s < 2; s++) {
                            int nt = h * 4 + p * 2 + s;
                            mma_bf16(acc[mt][nt], ahi[mt], bhi[p][s * 2], bhi[p][s * 2 + 1]);
                            mma_bf16(acc[mt][nt], ahi[mt], blo[p][s * 2], blo[p][s * 2 + 1]);
                            mma_bf16(acc[mt][nt], alo[mt], bhi[p][s * 2], bhi[p][s * 2 + 1]);
                        }
                    }
                }
            }
        }
    }

    // ---- epilogue: bias (+relu), fp32 stores (+ optional bf16 split) ----
    int c_r = lane >> 2;
    int c_c = (lane & 3) * 2;
    bool wsplit = (o_hi != nullptr);
#pragma unroll
    for (int mt = 0; mt < 2; mt++) {
        int r0 = rowbase + warp_m + mt * 16 + c_r;
        int r1 = r0 + 8;
#pragma unroll
        for (int nt = 0; nt < 8; nt++) {
            int c = warp_n + nt * 8 + c_c;
            float v0 = acc[mt][nt][0] + bs[c];
            float v1 = acc[mt][nt][1] + bs[c + 1];
            float v2 = acc[mt][nt][2] + bs[c];
            float v3 = acc[mt][nt][3] + bs[c + 1];
            if (do_relu) {
                v0 = fmaxf(v0, 0.f); v1 = fmaxf(v1, 0.f);
                v2 = fmaxf(v2, 0.f); v3 = fmaxf(v3, 0.f);
            }
            if (r0 < nrows) {
                *(float2*)(out + (size_t)r0 * DIM + c) = make_float2(v0, v1);
                if (wsplit) {
                    uint32_t hh, ll;
                    split2(v0, v1, hh, ll);
                    o_hi[(size_t)r0 * DIM2 + (c >> 1)] = hh;
                    o_lo[(size_t)r0 * DIM2 + (c >> 1)] = ll;
                }
            }
            if (r1 < nrows) {
                *(float2*)(out + (size_t)r1 * DIM + c) = make_float2(v2, v3);
                if (wsplit) {
                    uint32_t hh, ll;
                    split2(v2, v3, hh, ll);
                    o_hi[(size_t)r1 * DIM2 + (c >> 1)] = hh;
                    o_lo[(size_t)r1 * DIM2 + (c >> 1)] = ll;
                }
            }
        }
    }
}

// ---------------------------------------------------------------------------
extern "C" void kernel_launch(void* const* d_in, const int* in_sizes, int n_in,
                              void* d_out, int out_size)
{
    const float* x   = (const float*)d_in[0];
    const int*   src = (const int*)  d_in[1];
    const int*   dst = (const int*)  d_in[2];
    const float* wt  = (const float*)d_in[3];
    const float* Ws1 = (const float*)d_in[4];
    const float* Wn1 = (const float*)d_in[5];
    const float* b1  = (const float*)d_in[6];
    const float* Ws2 = (const float*)d_in[7];
    const float* Wn2 = (const float*)d_in[8];
    const float* b2  = (const float*)d_in[9];
    float* out = (float*)d_out;

    int E = in_sizes[1];

    int *cnt, *row, *cur, *bsum, *bofs, *esrc;
    float *ew, *h1;
    uint32_t *xh, *xl, *h1h, *h1l, *hnh, *hnl, *wh, *wl;
    cudaGetSymbolAddress((void**)&cnt,  g_cnt);
    cudaGetSymbolAddress((void**)&row,  g_row);
    cudaGetSymbolAddress((void**)&cur,  g_cur);
    cudaGetSymbolAddress((void**)&bsum, g_bsum);
    cudaGetSymbolAddress((void**)&bofs, g_bofs);
    cudaGetSymbolAddress((void**)&esrc, g_esrc);
    cudaGetSymbolAddress((void**)&ew,   g_ew);
    cudaGetSymbolAddress((void**)&h1,   g_h1);
    cudaGetSymbolAddress((void**)&xh,   g_xh);
    cudaGetSymbolAddress((void**)&xl,   g_xl);
    cudaGetSymbolAddress((void**)&h1h,  g_h1h);
    cudaGetSymbolAddress((void**)&h1l,  g_h1l);
    cudaGetSymbolAddress((void**)&hnh,  g_hnh);
    cudaGetSymbolAddress((void**)&hnl,  g_hnl);
    cudaGetSymbolAddress((void**)&wh,   g_wh);
    cudaGetSymbolAddress((void**)&wl,   g_wl);

    int eblocks  = (E + 255) / 256;
    int gblocks  = (N_NODES + MM_TILE - 1) / MM_TILE;   // 391
    int nwblocks = (N_NODES + 7) / 8;

    // ---- CSR build (by dst) ----
    zero_kernel<<<64, 256>>>((float4*)cnt, N_NODES / 4);
    hist_kernel<<<eblocks, 256>>>(dst, cnt, E);
    scan_bsum_kernel<<<SCAN_NB, SCAN_BLK>>>(cnt, bsum);
    scan_bofs_kernel<<<1, SCAN_BLK>>>(bsum, bofs, row);
    scan_write_kernel<<<SCAN_NB, SCAN_BLK>>>(cnt, bofs, row, cur);
    scatter_kernel<<<eblocks, 256>>>(src, dst, wt, cur, esrc, ew, E);

    // ---- operand preconversion (W: 4 x 16K elems; x: 6.4M elems) ----
    split_kernel<<<16, 256>>>((const float2*)Ws1, wh,         wl,         DIM * DIM2);
    split_kernel<<<16, 256>>>((const float2*)Wn1, wh + 8192,  wl + 8192,  DIM * DIM2);
    split_kernel<<<16, 256>>>((const float2*)Ws2, wh + 16384, wl + 16384, DIM * DIM2);
    split_kernel<<<16, 256>>>((const float2*)Wn2, wh + 24576, wl + 24576, DIM * DIM2);
    split_kernel<<<512, 256>>>((const float2*)x, xh, xl, N_NODES * DIM2);

    // ---- layer 1 ----
    gather_kernel<<<nwblocks, 256>>>(x, row, esrc, ew, hnh, hnl);
    sage_gemm_mma<<<gblocks, 256>>>(xh, xl, hnh, hnl, wh, wl, b1,
                                    h1, h1h, h1l, N_NODES, 1);

    // ---- layer 2 ----
    gather_kernel<<<nwblocks, 256>>>(h1, row, esrc, ew, hnh, hnl);
    sage_gemm_mma<<<gblocks, 256>>>(h1h, h1l, hnh, hnl, wh + 16384, wl + 16384, b2,
                                    out, nullptr, nullptr, N_NODES, 0);
}

// round 10
// speedup vs baseline: 1.2912x; 1.2912x over previous
#include <cuda_runtime.h>
#include <cuda_bf16.h>
#include <cstdint>

#define N_NODES 50000
#define E_MAX   625000
#define DIM     128

// ---------------------------------------------------------------------------
// Static device scratch (no runtime allocation)
// ---------------------------------------------------------------------------
__device__ int   g_cnt[N_NODES];
__device__ int   g_row[N_NODES + 1];
__device__ int   g_cur[N_NODES];
__device__ int   g_bsum[256];
__device__ uint2 g_edge[E_MAX];                    // interleaved {src, weight-bits}
__device__ float g_h1[(size_t)N_NODES * DIM];
__device__ float g_hn[(size_t)N_NODES * DIM];

#define SCAN_BLK 256
#define SCAN_NB  ((N_NODES + SCAN_BLK - 1) / SCAN_BLK)   // 196

// ---------------------------------------------------------------------------
// CSR build, step 1: histogram of dst (cnt pre-zeroed by cudaMemsetAsync)
// ---------------------------------------------------------------------------
__global__ void hist_kernel(const int* __restrict__ dst, int* __restrict__ cnt, int E) {
    int i = blockIdx.x * blockDim.x + threadIdx.x;
    for (; i < E; i += gridDim.x * blockDim.x)
        atomicAdd(&cnt[dst[i]], 1);
}

// ---------------------------------------------------------------------------
// Scan pass A: per-block sums of cnt
// ---------------------------------------------------------------------------
__global__ void scan_bsum_kernel(const int* __restrict__ cnt, int* __restrict__ bsum) {
    __shared__ int sh[SCAN_BLK];
    int i = blockIdx.x * SCAN_BLK + threadIdx.x;
    int v = (i < N_NODES) ? cnt[i] : 0;
    sh[threadIdx.x] = v;
    __syncthreads();
    for (int off = SCAN_BLK / 2; off > 0; off >>= 1) {
        if (threadIdx.x < off) sh[threadIdx.x] += sh[threadIdx.x + off];
        __syncthreads();
    }
    if (threadIdx.x == 0) bsum[blockIdx.x] = sh[0];
}

// ---------------------------------------------------------------------------
// Scan pass B (fused): block offset = warp-reduced prefix of bsum, then local
// exclusive scan; writes row and cur. row[N_NODES] = E (statically known).
// ---------------------------------------------------------------------------
__global__ void scan_write_kernel(const int* __restrict__ cnt,
                                  const int* __restrict__ bsum,
                                  int* __restrict__ row,
                                  int* __restrict__ cur, int E) {
    __shared__ int sh[SCAN_BLK];
    __shared__ int base_sh;
    int t = threadIdx.x;
    int b = blockIdx.x;

    if (t < 32) {
        int s = 0;
        for (int i = t; i < b; i += 32) s += bsum[i];
#pragma unroll
        for (int o = 16; o > 0; o >>= 1) s += __shfl_down_sync(0xffffffffu, s, o);
        if (t == 0) base_sh = s;
    }

    int i = b * SCAN_BLK + t;
    int v = (i < N_NODES) ? cnt[i] : 0;
    sh[t] = v;
    __syncthreads();
    for (int off = 1; off < SCAN_BLK; off <<= 1) {
        int u = 0;
        if (t >= off) u = sh[t - off];
        __syncthreads();
        if (t >= off) sh[t] += u;
        __syncthreads();
    }
    if (i < N_NODES) {
        int r = base_sh + sh[t] - v;       // exclusive prefix + block offset
        row[i] = r;
        cur[i] = r;
    }
    if (i == 0) row[N_NODES] = E;
}

// ---------------------------------------------------------------------------
// CSR build, step 3: scatter edges into CSR slots (interleaved uint2)
// ---------------------------------------------------------------------------
__global__ void scatter_kernel(const int*   __restrict__ src,
                               const int*   __restrict__ dst,
                               const float* __restrict__ wt,
                               int*   __restrict__ cur,
                               uint2* __restrict__ edge,
                               int E)
{
    int i = blockIdx.x * blockDim.x + threadIdx.x;
    for (; i < E; i += gridDim.x * blockDim.x) {
        int p = atomicAdd(&cur[dst[i]], 1);
        edge[p] = make_uint2((uint32_t)src[i], __float_as_uint(wt[i]));
    }
}

// ---------------------------------------------------------------------------
// Gather: one warp per destination node; shfl-broadcast edge batch, MLP=4.
// Edge id+weight come from one 8B load per lane.
// ---------------------------------------------------------------------------
__global__ void gather_kernel(const float* __restrict__ h,
                              const int*   __restrict__ row,
                              const uint2* __restrict__ edge,
                              float*       __restrict__ hn)
{
    int warp = (blockIdx.x * blockDim.x + threadIdx.x) >> 5;
    int lane = threadIdx.x & 31;
    if (warp >= N_NODES) return;

    int rs = row[warp];
    int re = row[warp + 1];

    float4 acc = make_float4(0.f, 0.f, 0.f, 0.f);

    for (int base = rs; base < re; base += 32) {
        int cnt = re - base; if (cnt > 32) cnt = 32;
        int   s_l = 0; float w_l = 0.f;
        if (lane < cnt) {
            uint2 ev = edge[base + lane];
            s_l = (int)ev.x;
            w_l = __uint_as_float(ev.y);
        }

        for (int j = 0; j < cnt; j += 4) {
            int valid = cnt - j; if (valid > 4) valid = 4;
            float4 v[4]; float wj[4];
#pragma unroll
            for (int u = 0; u < 4; u++) {
                int   s = __shfl_sync(0xffffffffu, s_l, j + u);
                float w = __shfl_sync(0xffffffffu, w_l, j + u);
                if (u < valid) {
                    v[u]  = *(const float4*)(h + (size_t)s * DIM + lane * 4);
                    wj[u] = w;
                }
            }
#pragma unroll
            for (int u = 0; u < 4; u++) {
                if (u < valid) {
                    acc.x += wj[u] * v[u].x;
                    acc.y += wj[u] * v[u].y;
                    acc.z += wj[u] * v[u].z;
                    acc.w += wj[u] * v[u].w;
                }
            }
        }
    }

    float inv = 1.0f / fmaxf((float)(re - rs), 1.0f);
    acc.x *= inv; acc.y *= inv; acc.z *= inv; acc.w *= inv;
    *(float4*)(hn + (size_t)warp * DIM + lane * 4) = acc;
}

// ---------------------------------------------------------------------------
// SAGE GEMM (R7): mma.sync bf16 split-precision (hi+lo; drop lo*lo).
//   out[r, j] = sum_k h[r,k]*Ws[j,k] + hn[r,k]*Wn[j,k] + b[j]
// CTA: 128x128 tile, 256 threads = 8 warps (4m x 2n); warp tile 32x64.
// K = 256 in 8 chunks of 32; per chunk convert fp32 -> bf16 hi/lo in smem,
// then mma.m16n8k16 for 3 terms (hi*hi, hi*lo, lo*hi), fp32 accumulation.
// ---------------------------------------------------------------------------
#define MM_TILE 128
#define STR 40   // smem row stride in bf16 elems (80B: 16B-aligned, conflict-free ldmatrix)

__device__ __forceinline__ void ldm4(uint32_t (&r)[4], uint32_t addr) {
    asm volatile("ldmatrix.sync.aligned.m8n8.x4.shared.b16 {%0,%1,%2,%3}, [%4];"
                 : "=r"(r[0]), "=r"(r[1]), "=r"(r[2]), "=r"(r[3]) : "r"(addr));
}
__device__ __forceinline__ void mma_bf16(float (&c)[4], const uint32_t (&a)[4],
                                         uint32_t b0, uint32_t b1) {
    asm volatile("mma.sync.aligned.m16n8k16.row.col.f32.bf16.bf16.f32 "
                 "{%0,%1,%2,%3}, {%4,%5,%6,%7}, {%8,%9}, {%0,%1,%2,%3};"
                 : "+f"(c[0]), "+f"(c[1]), "+f"(c[2]), "+f"(c[3])
                 : "r"(a[0]), "r"(a[1]), "r"(a[2]), "r"(a[3]), "r"(b0), "r"(b1));
}
__device__ __forceinline__ uint32_t smem_u32(const void* p) {
    uint32_t a;
    asm("{ .reg .u64 t; cvta.to.shared.u64 t, %1; cvt.u32.u64 %0, t; }" : "=r"(a) : "l"(p));
    return a;
}
__device__ __forceinline__ uint32_t packbf(float a, float b) {
    __nv_bfloat162 t = __floats2bfloat162_rn(a, b);
    return *(uint32_t*)&t;
}
__device__ __forceinline__ void split2(float x, float y, uint32_t& hi, uint32_t& lo) {
    float hx = __bfloat162float(__float2bfloat16_rn(x));
    float hy = __bfloat162float(__float2bfloat16_rn(y));
    hi = packbf(hx, hy);
    lo = packbf(x - hx, y - hy);
}

__global__ void sage_gemm_mma(const float* __restrict__ Aself,
                              const float* __restrict__ Aneigh,  // already deg-scaled
                              const float* __restrict__ Ws,
                              const float* __restrict__ Wn,
                              const float* __restrict__ bias,
                              float*       __restrict__ out,
                              int nrows, int do_relu)
{
    __shared__ __align__(16) unsigned short Ah[MM_TILE * STR];
    __shared__ __align__(16) unsigned short Al[MM_TILE * STR];
    __shared__ __align__(16) unsigned short Bh[MM_TILE * STR];
    __shared__ __align__(16) unsigned short Bl[MM_TILE * STR];
    __shared__ float bs[DIM];

    int tid  = threadIdx.x;
    int wid  = tid >> 5;
    int lane = tid & 31;
    int warp_m = (wid & 3) * 32;
    int warp_n = (wid >> 2) * 64;
    int rowbase = blockIdx.x * MM_TILE;

    if (tid < DIM) bs[tid] = bias[tid];

    float acc[2][8][4];
#pragma unroll
    for (int mt = 0; mt < 2; mt++)
#pragma unroll
        for (int nt = 0; nt < 8; nt++)
#pragma unroll
            for (int e = 0; e < 4; e++) acc[mt][nt][e] = 0.f;

    uint32_t ah_base = smem_u32(Ah), al_base = smem_u32(Al);
    uint32_t bh_base = smem_u32(Bh), bl_base = smem_u32(Bl);

    // ldmatrix lane address components
    int a_r = lane & 15;
    int a_c = (lane >> 4) << 3;
    int b_g = lane >> 3;
    int b_r = lane & 7;
    int b_nofs = ((b_g >> 1) << 3) + b_r;
    int b_kofs = (b_g & 1) << 3;

    for (int chunk = 0; chunk < 8; chunk++) {
        const float* As; const float* W; int kb = (chunk & 3) * 32;
        if (chunk < 4) { As = Aself;  W = Ws; }
        else           { As = Aneigh; W = Wn; }

        __syncthreads();   // protect previous chunk's reads

        // ---- convert A chunk: 128 rows x 32 cols -> hi/lo ----
#pragma unroll
        for (int it = 0; it < 4; it++) {
            int idx = it * 256 + tid;    // 0..1023 float4s
            int r = idx >> 3;            // 0..127
            int q = idx & 7;             // 0..7 (quad of 4 floats)
            int gr = rowbase + r; if (gr > nrows - 1) gr = nrows - 1;
            float4 v = *(const float4*)(As + (size_t)gr * DIM + kb + q * 4);
            uint32_t h0, l0, h1, l1;
            split2(v.x, v.y, h0, l0);
            split2(v.z, v.w, h1, l1);
            uint32_t* ph = (uint32_t*)&Ah[r * STR + q * 4];
            uint32_t* pl = (uint32_t*)&Al[r * STR + q * 4];
            ph[0] = h0; ph[1] = h1;
            pl[0] = l0; pl[1] = l1;
        }
        // ---- convert W chunk: 128 rows (j) x 32 cols ----
#pragma unroll
        for (int it = 0; it < 4; it++) {
            int idx = it * 256 + tid;
            int r = idx >> 3;
            int q = idx & 7;
            float4 v = *(const float4*)(W + (size_t)r * DIM + kb + q * 4);
            uint32_t h0, l0, h1, l1;
            split2(v.x, v.y, h0, l0);
            split2(v.z, v.w, h1, l1);
            uint32_t* ph = (uint32_t*)&Bh[r * STR + q * 4];
            uint32_t* pl = (uint32_t*)&Bl[r * STR + q * 4];
            ph[0] = h0; ph[1] = h1;
            pl[0] = l0; pl[1] = l1;
        }
        __syncthreads();

        // ---- MMA: 2 k-steps of 16 ----
#pragma unroll
        for (int ks = 0; ks < 2; ks++) {
            int k0 = ks * 16;

            uint32_t ahi[2][4], alo[2][4];
#pragma unroll
            for (int mt = 0; mt < 2; mt++) {
                uint32_t off = (uint32_t)((warp_m + mt * 16 + a_r) * STR + k0 + a_c) * 2;
                ldm4(ahi[mt], ah_base + off);
                ldm4(alo[mt], al_base + off);
            }

#pragma unroll
            for (int h = 0; h < 2; h++) {
                uint32_t bhi[2][4], blo[2][4];
#pragma unroll
                for (int p = 0; p < 2; p++) {
                    int n0 = warp_n + h * 32 + p * 16;
                    uint32_t off = (uint32_t)((n0 + b_nofs) * STR + k0 + b_kofs) * 2;
                    ldm4(bhi[p], bh_base + off);
                    ldm4(blo[p], bl_base + off);
                }
#pragma unroll
                for (int mt = 0; mt < 2; mt++) {
#pragma unroll
                    for (int p = 0; p < 2; p++) {
#pragma unroll
                        for (int s = 0; s < 2; s++) {
                            int nt = h * 4 + p * 2 + s;
                            mma_bf16(acc[mt][nt], ahi[mt], bhi[p][s * 2], bhi[p][s * 2 + 1]);
                            mma_bf16(acc[mt][nt], ahi[mt], blo[p][s * 2], blo[p][s * 2 + 1]);
                            mma_bf16(acc[mt][nt], alo[mt], bhi[p][s * 2], bhi[p][s * 2 + 1]);
                        }
                    }
                }
            }
        }
    }

    // ---- epilogue: bias (+relu), float2 stores ----
    int c_r = lane >> 2;
    int c_c = (lane & 3) * 2;
#pragma unroll
    for (int mt = 0; mt < 2; mt++) {
        int r0 = rowbase + warp_m + mt * 16 + c_r;
        int r1 = r0 + 8;
#pragma unroll
        for (int nt = 0; nt < 8; nt++) {
            int c = warp_n + nt * 8 + c_c;
            float v0 = acc[mt][nt][0] + bs[c];
            float v1 = acc[mt][nt][1] + bs[c + 1];
            float v2 = acc[mt][nt][2] + bs[c];
            float v3 = acc[mt][nt][3] + bs[c + 1];
            if (do_relu) {
                v0 = fmaxf(v0, 0.f); v1 = fmaxf(v1, 0.f);
                v2 = fmaxf(v2, 0.f); v3 = fmaxf(v3, 0.f);
            }
            if (r0 < nrows) *(float2*)(out + (size_t)r0 * DIM + c) = make_float2(v0, v1);
            if (r1 < nrows) *(float2*)(out + (size_t)r1 * DIM + c) = make_float2(v2, v3);
        }
    }
}

// ---------------------------------------------------------------------------
extern "C" void kernel_launch(void* const* d_in, const int* in_sizes, int n_in,
                              void* d_out, int out_size)
{
    const float* x   = (const float*)d_in[0];
    const int*   src = (const int*)  d_in[1];
    const int*   dst = (const int*)  d_in[2];
    const float* wt  = (const float*)d_in[3];
    const float* Ws1 = (const float*)d_in[4];
    const float* Wn1 = (const float*)d_in[5];
    const float* b1  = (const float*)d_in[6];
    const float* Ws2 = (const float*)d_in[7];
    const float* Wn2 = (const float*)d_in[8];
    const float* b2  = (const float*)d_in[9];
    float* out = (float*)d_out;

    int E = in_sizes[1];

    int *cnt, *row, *cur, *bsum;
    uint2 *edge;
    float *h1, *hn;
    cudaGetSymbolAddress((void**)&cnt,  g_cnt);
    cudaGetSymbolAddress((void**)&row,  g_row);
    cudaGetSymbolAddress((void**)&cur,  g_cur);
    cudaGetSymbolAddress((void**)&bsum, g_bsum);
    cudaGetSymbolAddress((void**)&edge, g_edge);
    cudaGetSymbolAddress((void**)&h1,   g_h1);
    cudaGetSymbolAddress((void**)&hn,   g_hn);

    int eblocks  = (E + 255) / 256;
    int gblocks  = (N_NODES + MM_TILE - 1) / MM_TILE;   // 391
    int nwblocks = (N_NODES + 7) / 8;

    // ---- CSR build (by dst); memset node is not a kernel launch ----
    cudaMemsetAsync(cnt, 0, N_NODES * sizeof(int));
    hist_kernel<<<eblocks, 256>>>(dst, cnt, E);                       // launch 0
    scan_bsum_kernel<<<SCAN_NB, SCAN_BLK>>>(cnt, bsum);               // launch 1
    scan_write_kernel<<<SCAN_NB, SCAN_BLK>>>(cnt, bsum, row, cur, E); // launch 2
    scatter_kernel<<<eblocks, 256>>>(src, dst, wt, cur, edge, E);     // launch 3

    // ---- layer 1 ----
    gather_kernel<<<nwblocks, 256>>>(x, row, edge, hn);               // launch 4
    sage_gemm_mma<<<gblocks, 256>>>(x, hn, Ws1, Wn1, b1, h1, N_NODES, 1);   // launch 5 (ncu)

    // ---- layer 2 ----
    gather_kernel<<<nwblocks, 256>>>(h1, row, edge, hn);              // launch 6
    sage_gemm_mma<<<gblocks, 256>>>(h1, hn, Ws2, Wn2, b2, out, N_NODES, 0); // launch 7
}

// round 11
// speedup vs baseline: 1.3933x; 1.0791x over previous
#include <cuda_runtime.h>
#include <cuda_bf16.h>
#include <cstdint>

#define N_NODES 50000
#define E_MAX   625000
#define DIM     128

// ---------------------------------------------------------------------------
// Static device scratch (no runtime allocation)
// ---------------------------------------------------------------------------
__device__ int      g_cnt[N_NODES];
__device__ int      g_row[N_NODES + 1];
__device__ int      g_cur[N_NODES];
__device__ int      g_bsum[256];
__device__ uint2    g_edge[E_MAX];                 // interleaved {src, weight-bits}
__device__ float    g_h1[(size_t)N_NODES * DIM];
__device__ float    g_hn[(size_t)N_NODES * DIM];
__device__ uint32_t g_wh[4 * 8192];                // W bf16-hi: Ws1|Wn1|Ws2|Wn2 (bf16x2 words)
__device__ uint32_t g_wl[4 * 8192];                // W bf16-lo

#define SCAN_BLK 256
#define SCAN_NB  ((N_NODES + SCAN_BLK - 1) / SCAN_BLK)   // 196

// ---------------------------------------------------------------------------
__device__ __forceinline__ uint32_t packbf(float a, float b) {
    __nv_bfloat162 t = __floats2bfloat162_rn(a, b);
    return *(uint32_t*)&t;
}
__device__ __forceinline__ void split2(float x, float y, uint32_t& hi, uint32_t& lo) {
    float hx = __bfloat162float(__float2bfloat16_rn(x));
    float hy = __bfloat162float(__float2bfloat16_rn(y));
    hi = packbf(hx, hy);
    lo = packbf(x - hx, y - hy);
}

// ---------------------------------------------------------------------------
// CSR build
// ---------------------------------------------------------------------------
__global__ void hist_kernel(const int* __restrict__ dst, int* __restrict__ cnt, int E) {
    int i = blockIdx.x * blockDim.x + threadIdx.x;
    for (; i < E; i += gridDim.x * blockDim.x)
        atomicAdd(&cnt[dst[i]], 1);
}

__global__ void scan_bsum_kernel(const int* __restrict__ cnt, int* __restrict__ bsum) {
    __shared__ int sh[SCAN_BLK];
    int i = blockIdx.x * SCAN_BLK + threadIdx.x;
    int v = (i < N_NODES) ? cnt[i] : 0;
    sh[threadIdx.x] = v;
    __syncthreads();
    for (int off = SCAN_BLK / 2; off > 0; off >>= 1) {
        if (threadIdx.x < off) sh[threadIdx.x] += sh[threadIdx.x + off];
        __syncthreads();
    }
    if (threadIdx.x == 0) bsum[blockIdx.x] = sh[0];
}

__global__ void scan_write_kernel(const int* __restrict__ cnt,
                                  const int* __restrict__ bsum,
                                  int* __restrict__ row,
                                  int* __restrict__ cur, int E) {
    __shared__ int sh[SCAN_BLK];
    __shared__ int base_sh;
    int t = threadIdx.x;
    int b = blockIdx.x;

    if (t < 32) {
        int s = 0;
        for (int i = t; i < b; i += 32) s += bsum[i];
#pragma unroll
        for (int o = 16; o > 0; o >>= 1) s += __shfl_down_sync(0xffffffffu, s, o);
        if (t == 0) base_sh = s;
    }

    int i = b * SCAN_BLK + t;
    int v = (i < N_NODES) ? cnt[i] : 0;
    sh[t] = v;
    __syncthreads();
    for (int off = 1; off < SCAN_BLK; off <<= 1) {
        int u = 0;
        if (t >= off) u = sh[t - off];
        __syncthreads();
        if (t >= off) sh[t] += u;
        __syncthreads();
    }
    if (i < N_NODES) {
        int r = base_sh + sh[t] - v;
        row[i] = r;
        cur[i] = r;
    }
    if (i == 0) row[N_NODES] = E;
}

__global__ void scatter_kernel(const int*   __restrict__ src,
                               const int*   __restrict__ dst,
                               const float* __restrict__ wt,
                               int*   __restrict__ cur,
                               uint2* __restrict__ edge,
                               int E)
{
    int i = blockIdx.x * blockDim.x + threadIdx.x;
    for (; i < E; i += gridDim.x * blockDim.x) {
        int p = atomicAdd(&cur[dst[i]], 1);
        edge[p] = make_uint2((uint32_t)src[i], __float_as_uint(wt[i]));
    }
}

// ---------------------------------------------------------------------------
// W pre-split: all 4 weight matrices -> bf16 hi/lo (bf16x2 words), one pass.
// ---------------------------------------------------------------------------
__global__ void split_w_kernel(const float2* __restrict__ Ws1, const float2* __restrict__ Wn1,
                               const float2* __restrict__ Ws2, const float2* __restrict__ Wn2,
                               uint32_t* __restrict__ wh, uint32_t* __restrict__ wl)
{
    int i = blockIdx.x * blockDim.x + threadIdx.x;   // 0..32767
    if (i >= 4 * 8192) return;
    int m = i >> 13, j = i & 8191;
    const float2* W = (m == 0) ? Ws1 : (m == 1) ? Wn1 : (m == 2) ? Ws2 : Wn2;
    float2 v = W[j];
    uint32_t h, l;
    split2(v.x, v.y, h, l);
    wh[i] = h;
    wl[i] = l;
}

// ---------------------------------------------------------------------------
// Gather: one warp per destination node; shfl-broadcast edge batch, MLP=4.
// ---------------------------------------------------------------------------
__global__ void gather_kernel(const float* __restrict__ h,
                              const int*   __restrict__ row,
                              const uint2* __restrict__ edge,
                              float*       __restrict__ hn)
{
    int warp = (blockIdx.x * blockDim.x + threadIdx.x) >> 5;
    int lane = threadIdx.x & 31;
    if (warp >= N_NODES) return;

    int rs = row[warp];
    int re = row[warp + 1];

    float4 acc = make_float4(0.f, 0.f, 0.f, 0.f);

    for (int base = rs; base < re; base += 32) {
        int cnt = re - base; if (cnt > 32) cnt = 32;
        int   s_l = 0; float w_l = 0.f;
        if (lane < cnt) {
            uint2 ev = edge[base + lane];
            s_l = (int)ev.x;
            w_l = __uint_as_float(ev.y);
        }

        for (int j = 0; j < cnt; j += 4) {
            int valid = cnt - j; if (valid > 4) valid = 4;
            float4 v[4]; float wj[4];
#pragma unroll
            for (int u = 0; u < 4; u++) {
                int   s = __shfl_sync(0xffffffffu, s_l, j + u);
                float w = __shfl_sync(0xffffffffu, w_l, j + u);
                if (u < valid) {
                    v[u]  = *(const float4*)(h + (size_t)s * DIM + lane * 4);
                    wj[u] = w;
                }
            }
#pragma unroll
            for (int u = 0; u < 4; u++) {
                if (u < valid) {
                    acc.x += wj[u] * v[u].x;
                    acc.y += wj[u] * v[u].y;
                    acc.z += wj[u] * v[u].z;
                    acc.w += wj[u] * v[u].w;
                }
            }
        }
    }

    float inv = 1.0f / fmaxf((float)(re - rs), 1.0f);
    acc.x *= inv; acc.y *= inv; acc.z *= inv; acc.w *= inv;
    *(float4*)(hn + (size_t)warp * DIM + lane * 4) = acc;
}

// ---------------------------------------------------------------------------
// SAGE GEMM v9: mma.sync bf16 split-precision, cp.async-pipelined.
//   out[r, j] = sum_k h[r,k]*Ws[j,k] + hn[r,k]*Wn[j,k] + b[j]
// CTA: 128x128 tile, 256 threads = 8 warps (4m x 2n); warp tile 32x64.
// K = 256 in 8 chunks of 32:
//   - A (fp32) cp.async double-buffered into smem stage; convert reads smem.
//   - W preconverted to global bf16 hi/lo; plain LDG->STS copy, no convert.
//   - MMA: 3 terms (hi*hi, hi*lo, lo*hi), fp32 accumulation.
// Dynamic smem layout (bytes):
//   Ah[0,10240) Al[10240,20480) Bh[20480,30720) Bl[30720,40960)
//   StageF[40960,73728)  (2 x 16KB fp32 A chunks)
//   bs [73728,74240)
// ---------------------------------------------------------------------------
#define MM_TILE 128
#define STR 40
#define SMO_AH 0
#define SMO_AL 10240
#define SMO_BH 20480
#define SMO_BL 30720
#define SMO_ST 40960
#define SMO_BS 73728
#define SM_TOTAL 74240

__device__ __forceinline__ void ldm4(uint32_t (&r)[4], uint32_t addr) {
    asm volatile("ldmatrix.sync.aligned.m8n8.x4.shared.b16 {%0,%1,%2,%3}, [%4];"
                 : "=r"(r[0]), "=r"(r[1]), "=r"(r[2]), "=r"(r[3]) : "r"(addr));
}
__device__ __forceinline__ void mma_bf16(float (&c)[4], const uint32_t (&a)[4],
                                         uint32_t b0, uint32_t b1) {
    asm volatile("mma.sync.aligned.m16n8k16.row.col.f32.bf16.bf16.f32 "
                 "{%0,%1,%2,%3}, {%4,%5,%6,%7}, {%8,%9}, {%0,%1,%2,%3};"
                 : "+f"(c[0]), "+f"(c[1]), "+f"(c[2]), "+f"(c[3])
                 : "r"(a[0]), "r"(a[1]), "r"(a[2]), "r"(a[3]), "r"(b0), "r"(b1));
}
__device__ __forceinline__ uint32_t smem_u32(const void* p) {
    uint32_t a;
    asm("{ .reg .u64 t; cvta.to.shared.u64 t, %1; cvt.u32.u64 %0, t; }" : "=r"(a) : "l"(p));
    return a;
}
__device__ __forceinline__ void cpasync16(uint32_t dst, const void* src) {
    asm volatile("cp.async.ca.shared.global [%0], [%1], 16;" :: "r"(dst), "l"(src));
}

__global__ void sage_gemm_mma(const float* __restrict__ Aself,
                              const float* __restrict__ Aneigh,   // already deg-scaled
                              const uint32_t* __restrict__ wh,    // layer base: [self 8192 | neigh 8192]
                              const uint32_t* __restrict__ wl,
                              const float* __restrict__ bias,
                              float*       __restrict__ out,
                              int nrows, int do_relu)
{
    extern __shared__ char smem[];
    unsigned short* Ah = (unsigned short*)(smem + SMO_AH);
    unsigned short* Al = (unsigned short*)(smem + SMO_AL);
    unsigned short* Bh = (unsigned short*)(smem + SMO_BH);
    unsigned short* Bl = (unsigned short*)(smem + SMO_BL);
    float* StageF = (float*)(smem + SMO_ST);
    float* bs = (float*)(smem + SMO_BS);

    int tid  = threadIdx.x;
    int wid  = tid >> 5;
    int lane = tid & 31;
    int warp_m = (wid & 3) * 32;
    int warp_n = (wid >> 2) * 64;
    int rowbase = blockIdx.x * MM_TILE;

    if (tid < DIM) bs[tid] = bias[tid];

    float acc[2][8][4];
#pragma unroll
    for (int mt = 0; mt < 2; mt++)
#pragma unroll
        for (int nt = 0; nt < 8; nt++)
#pragma unroll
            for (int e = 0; e < 4; e++) acc[mt][nt][e] = 0.f;

    uint32_t ah_base = smem_u32(Ah), al_base = smem_u32(Al);
    uint32_t bh_base = smem_u32(Bh), bl_base = smem_u32(Bl);
    uint32_t st_base = smem_u32(StageF);

    // ldmatrix lane address components
    int a_r = lane & 15;
    int a_c = (lane >> 4) << 3;
    int b_g = lane >> 3;
    int b_r = lane & 7;
    int b_nofs = ((b_g >> 1) << 3) + b_r;
    int b_kofs = (b_g & 1) << 3;

    // A stage mapping (per thread, 4 cp.asyncs / chunk): idx = it*256+tid
    // r = idx>>3 (0..127), q = idx&7; global row clamped once.
    int s_r0 = tid >> 3;       // rows s_r0 + it*32
    int s_q  = tid & 7;

    // ---- prologue: cp.async chunk 0 (A = Aself, kb=0) ----
    {
#pragma unroll
        for (int it = 0; it < 4; it++) {
            int r = s_r0 + it * 32;
            int gr = rowbase + r; if (gr > nrows - 1) gr = nrows - 1;
            cpasync16(st_base + (uint32_t)(r * 32 + s_q * 4) * 4,
                      Aself + (size_t)gr * DIM + s_q * 4);
        }
        asm volatile("cp.async.commit_group;");
    }

    for (int chunk = 0; chunk < 8; chunk++) {
        // ---- issue next chunk's A into the other stage buffer ----
        if (chunk < 7) {
            int nc = chunk + 1;
            const float* As = (nc < 4) ? Aself : Aneigh;
            int kb = (nc & 3) * 32;
            uint32_t stb = st_base + ((nc & 1) ? 16384u : 0u);
#pragma unroll
            for (int it = 0; it < 4; it++) {
                int r = s_r0 + it * 32;
                int gr = rowbase + r; if (gr > nrows - 1) gr = nrows - 1;
                cpasync16(stb + (uint32_t)(r * 32 + s_q * 4) * 4,
                          As + (size_t)gr * DIM + kb + s_q * 4);
            }
            asm volatile("cp.async.commit_group;");
            asm volatile("cp.async.wait_group 1;");
        } else {
            asm volatile("cp.async.wait_group 0;");
        }
        __syncthreads();   // stage[chunk&1] ready for all; prev MMA reads done

        // ---- convert A chunk from stage (LDS) -> Ah/Al ----
        {
            const float* st = StageF + ((chunk & 1) ? 4096 : 0);
#pragma unroll
            for (int it = 0; it < 4; it++) {
                int r = s_r0 + it * 32;
                float4 v = *(const float4*)(st + r * 32 + s_q * 4);
                uint32_t h0, l0, h1, l1;
                split2(v.x, v.y, h0, l0);
                split2(v.z, v.w, h1, l1);
                uint32_t* ph = (uint32_t*)&Ah[r * STR + s_q * 4];
                uint32_t* pl = (uint32_t*)&Al[r * STR + s_q * 4];
                ph[0] = h0; ph[1] = h1;
                pl[0] = l0; pl[1] = l1;
            }
        }
        // ---- copy W chunk (pre-split bf16) -> Bh/Bl ----
        {
            const uint32_t* pwh = wh + ((chunk < 4) ? 0 : 8192);
            const uint32_t* pwl = wl + ((chunk < 4) ? 0 : 8192);
            int kb2 = (chunk & 3) * 16;
#pragma unroll
            for (int it = 0; it < 2; it++) {
                int idx = it * 256 + tid;       // 0..511
                int r = idx >> 2, seg = idx & 3;
                uint4 vh = *(const uint4*)(pwh + r * 64 + kb2 + seg * 4);
                uint4 vl = *(const uint4*)(pwl + r * 64 + kb2 + seg * 4);
                *(uint4*)&Bh[r * STR + seg * 8] = vh;
                *(uint4*)&Bl[r * STR + seg * 8] = vl;
            }
        }
        __syncthreads();

        // ---- MMA: 2 k-steps of 16 ----
#pragma unroll
        for (int ks = 0; ks < 2; ks++) {
            int k0 = ks * 16;

            uint32_t ahi[2][4], alo[2][4];
#pragma unroll
            for (int mt = 0; mt < 2; mt++) {
                uint32_t off = (uint32_t)((warp_m + mt * 16 + a_r) * STR + k0 + a_c) * 2;
                ldm4(ahi[mt], ah_base + off);
                ldm4(alo[mt], al_base + off);
            }

#pragma unroll
            for (int h = 0; h < 2; h++) {
                uint32_t bhi[2][4], blo[2][4];
#pragma unroll
                for (int p = 0; p < 2; p++) {
                    int n0 = warp_n + h * 32 + p * 16;
                    uint32_t off = (uint32_t)((n0 + b_nofs) * STR + k0 + b_kofs) * 2;
                    ldm4(bhi[p], bh_base + off);
                    ldm4(blo[p], bl_base + off);
                }
#pragma unroll
                for (int mt = 0; mt < 2; mt++) {
#pragma unroll
                    for (int p = 0; p < 2; p++) {
#pragma unroll
                        for (int s = 0; s < 2; s++) {
                            int nt = h * 4 + p * 2 + s;
                            mma_bf16(acc[mt][nt], ahi[mt], bhi[p][s * 2], bhi[p][s * 2 + 1]);
                            mma_bf16(acc[mt][nt], ahi[mt], blo[p][s * 2], blo[p][s * 2 + 1]);
                            mma_bf16(acc[mt][nt], alo[mt], bhi[p][s * 2], bhi[p][s * 2 + 1]);
                        }
                    }
                }
            }
        }
        __syncthreads();   // MMA reads complete before next convert overwrites
    }

    // ---- epilogue: bias (+relu), float2 stores ----
    int c_r = lane >> 2;
    int c_c = (lane & 3) * 2;
#pragma unroll
    for (int mt = 0; mt < 2; mt++) {
        int r0 = rowbase + warp_m + mt * 16 + c_r;
        int r1 = r0 + 8;
#pragma unroll
        for (int nt = 0; nt < 8; nt++) {
            int c = warp_n + nt * 8 + c_c;
            float v0 = acc[mt][nt][0] + bs[c];
            float v1 = acc[mt][nt][1] + bs[c + 1];
            float v2 = acc[mt][nt][2] + bs[c];
            float v3 = acc[mt][nt][3] + bs[c + 1];
            if (do_relu) {
                v0 = fmaxf(v0, 0.f); v1 = fmaxf(v1, 0.f);
                v2 = fmaxf(v2, 0.f); v3 = fmaxf(v3, 0.f);
            }
            if (r0 < nrows) *(float2*)(out + (size_t)r0 * DIM + c) = make_float2(v0, v1);
            if (r1 < nrows) *(float2*)(out + (size_t)r1 * DIM + c) = make_float2(v2, v3);
        }
    }
}

// ---------------------------------------------------------------------------
extern "C" void kernel_launch(void* const* d_in, const int* in_sizes, int n_in,
                              void* d_out, int out_size)
{
    const float* x   = (const float*)d_in[0];
    const int*   src = (const int*)  d_in[1];
    const int*   dst = (const int*)  d_in[2];
    const float* wt  = (const float*)d_in[3];
    const float* Ws1 = (const float*)d_in[4];
    const float* Wn1 = (const float*)d_in[5];
    const float* b1  = (const float*)d_in[6];
    const float* Ws2 = (const float*)d_in[7];
    const float* Wn2 = (const float*)d_in[8];
    const float* b2  = (const float*)d_in[9];
    float* out = (float*)d_out;

    int E = in_sizes[1];

    int *cnt, *row, *cur, *bsum;
    uint2 *edge;
    float *h1, *hn;
    uint32_t *wh, *wl;
    cudaGetSymbolAddress((void**)&cnt,  g_cnt);
    cudaGetSymbolAddress((void**)&row,  g_row);
    cudaGetSymbolAddress((void**)&cur,  g_cur);
    cudaGetSymbolAddress((void**)&bsum, g_bsum);
    cudaGetSymbolAddress((void**)&edge, g_edge);
    cudaGetSymbolAddress((void**)&h1,   g_h1);
    cudaGetSymbolAddress((void**)&hn,   g_hn);
    cudaGetSymbolAddress((void**)&wh,   g_wh);
    cudaGetSymbolAddress((void**)&wl,   g_wl);

    static bool attr_set = false;
    if (!attr_set) {
        cudaFuncSetAttribute(sage_gemm_mma,
                             cudaFuncAttributeMaxDynamicSharedMemorySize, SM_TOTAL);
        attr_set = true;
    }

    int eblocks  = (E + 255) / 256;
    int gblocks  = (N_NODES + MM_TILE - 1) / MM_TILE;   // 391
    int nwblocks = (N_NODES + 7) / 8;

    // ---- CSR build (by dst) ----
    cudaMemsetAsync(cnt, 0, N_NODES * sizeof(int));
    hist_kernel<<<eblocks, 256>>>(dst, cnt, E);
    scan_bsum_kernel<<<SCAN_NB, SCAN_BLK>>>(cnt, bsum);
    scan_write_kernel<<<SCAN_NB, SCAN_BLK>>>(cnt, bsum, row, cur, E);
    scatter_kernel<<<eblocks, 256>>>(src, dst, wt, cur, edge, E);

    // ---- W pre-split (all 4 matrices) ----
    split_w_kernel<<<128, 256>>>((const float2*)Ws1, (const float2*)Wn1,
                                 (const float2*)Ws2, (const float2*)Wn2, wh, wl);

    // ---- layer 1 ----
    gather_kernel<<<nwblocks, 256>>>(x, row, edge, hn);
    sage_gemm_mma<<<gblocks, 256, SM_TOTAL>>>(x, hn, wh, wl, b1, h1, N_NODES, 1);

    // ---- layer 2 ----
    gather_kernel<<<nwblocks, 256>>>(h1, row, edge, hn);
    sage_gemm_mma<<<gblocks, 256, SM_TOTAL>>>(h1, hn, wh + 16384, wl + 16384, b2,
                                              out, N_NODES, 0);
}